// round 12
// baseline (speedup 1.0000x reference)
#include <cuda_runtime.h>
#include <cuda_bf16.h>
#include <math.h>
#include <stdint.h>

#define Bb 4
#define Nn 256
#define Tt 128
#define Ff 64
#define Kk 8
#define Hh 256
#define Ee 8

// ---- scratch (static __device__ per allocation rules) ----
__device__ __align__(16) float g_ht [Bb*Tt*Nn*Hh];            // h (B,T,N,H) fp32
__device__ __align__(16) float g_A  [Kk*Nn*Nn];               // row-normalized A
__device__ __align__(16) __nv_bfloat16 g_Ab [Bb*Kk*Nn*Nn];    // bf16 alpha*A (row-major i x j)
__device__ __align__(16) __nv_bfloat16 g_hbf[Bb*Tt*Hh*Nn];    // bf16 h transposed (B,T,H,N)
__device__ __align__(16) __nv_bfloat16 g_midbf[Bb*Tt*Nn*Hh];  // bf16 aggregation result (B,T,N,H)
__device__ __align__(16) __nv_bfloat16 g_owT[Hh*Hh];          // bf16 out_w transposed [h][f]
__device__             float g_ctxp[Bb*32*Ff];
__device__             float g_alpha[Bb*Kk];

typedef unsigned long long u64;

__device__ __forceinline__ u64 pk2(float x) {
    u64 r; asm("mov.b64 %0, {%1, %1};" : "=l"(r) : "f"(x)); return r;
}
__device__ __forceinline__ void fma2(u64 &d, u64 a, u64 b) {
    asm("fma.rn.f32x2 %0, %1, %2, %0;" : "+l"(d) : "l"(a), "l"(b));
}
__device__ __forceinline__ float2 u2f(u64 v) {
    float2 f; asm("mov.b64 {%0, %1}, %2;" : "=f"(f.x), "=f"(f.y) : "l"(v)); return f;
}
__device__ __forceinline__ float gelu_exact(float v) {
    return 0.5f * v * (1.0f + erff(v * 0.70710678118654752f));
}
__device__ __forceinline__ uint32_t smem_u32(const void* p) {
    uint32_t a; asm("{ .reg .u64 t; cvta.to.shared.u64 t, %1; cvt.u32.u64 %0, t; }" : "=r"(a) : "l"(p));
    return a;
}
__device__ __forceinline__ void cpa16(uint32_t dst, const void* src) {
    asm volatile("cp.async.cg.shared.global [%0], [%1], 16;" :: "r"(dst), "l"(src));
}
#define CP_COMMIT()  asm volatile("cp.async.commit_group;" ::: "memory")
#define CP_WAIT1()   asm volatile("cp.async.wait_group 1;" ::: "memory")
#define CP_WAIT0()   asm volatile("cp.async.wait_group 0;" ::: "memory")

__device__ __forceinline__ void ldsm_x4(uint32_t &r0, uint32_t &r1, uint32_t &r2, uint32_t &r3,
                                        uint32_t addr) {
    asm volatile("ldmatrix.sync.aligned.m8n8.x4.shared.b16 {%0,%1,%2,%3}, [%4];"
                 : "=r"(r0), "=r"(r1), "=r"(r2), "=r"(r3) : "r"(addr));
}
__device__ __forceinline__ void mma16816(float &c0, float &c1, float &c2, float &c3,
                                         uint32_t a0, uint32_t a1, uint32_t a2, uint32_t a3,
                                         uint32_t b0, uint32_t b1) {
    asm volatile("mma.sync.aligned.m16n8k16.row.col.f32.bf16.bf16.f32 "
                 "{%0,%1,%2,%3}, {%4,%5,%6,%7}, {%8,%9}, {%0,%1,%2,%3};"
                 : "+f"(c0), "+f"(c1), "+f"(c2), "+f"(c3)
                 : "r"(a0), "r"(a1), "r"(a2), "r"(a3), "r"(b0), "r"(b1));
}
__device__ __forceinline__ uint32_t packbf2(float x, float y) {
    __nv_bfloat162 p = __floats2bfloat162_rn(x, y);
    return *(uint32_t*)&p;
}

// ============================================================
// 1a) ctx partial sums
// ============================================================
__global__ void k_ctx_partial(const float* __restrict__ x) {
    int b = blockIdx.y, g = blockIdx.x;
    int tid = threadIdx.x;
    int fg = tid & 15, r = tid >> 4;
    const float4* xp = (const float4*)(x + (size_t)b * Nn * Tt * Ff);
    float4 s = make_float4(0.f, 0.f, 0.f, 0.f);
    int base = g * 1024;
    for (int idx = base + r; idx < base + 1024; idx += 16) {
        float4 v = xp[idx * 16 + fg];
        s.x += v.x; s.y += v.y; s.z += v.z; s.w += v.w;
    }
    __shared__ float sp[16][64];
    sp[r][fg*4+0] = s.x; sp[r][fg*4+1] = s.y; sp[r][fg*4+2] = s.z; sp[r][fg*4+3] = s.w;
    __syncthreads();
    if (tid < 64) {
        float acc = 0.f;
        #pragma unroll
        for (int rr = 0; rr < 16; rr++) acc += sp[rr][tid];
        g_ctxp[(b * 32 + g) * 64 + tid] = acc;
    }
}

// ============================================================
// 1b) ctx finish + gate MLP + alpha
// ============================================================
__global__ void k_small(const float* __restrict__ lag_embed,
                        const float* __restrict__ ctx_w1, const float* __restrict__ ctx_b1,
                        const float* __restrict__ ctx_w2, const float* __restrict__ ctx_b2,
                        const float* __restrict__ gate_w1, const float* __restrict__ gate_b1,
                        const float* __restrict__ gate_w2, const float* __restrict__ gate_b2) {
    __shared__ float sctx[Bb][Ff];
    __shared__ float sh1[Bb][Ee];
    __shared__ float scf[Bb][Ee];
    int tid = threadIdx.x;
    for (int p = tid; p < Bb * Ff; p += 64) {
        int b = p >> 6, f = p & 63;
        float s = 0.f;
        for (int g = 0; g < 32; g++) s += g_ctxp[(b * 32 + g) * 64 + f];
        sctx[b][f] = s * (1.0f / (Nn * Tt));
    }
    __syncthreads();
    if (tid < 32) {
        int b = tid >> 3, e = tid & 7;
        float v = ctx_b1[e];
        for (int f = 0; f < Ff; f++) v += sctx[b][f] * ctx_w1[f * Ee + e];
        sh1[b][e] = gelu_exact(v);
    }
    __syncthreads();
    if (tid < 32) {
        int b = tid >> 3, e = tid & 7;
        float v = ctx_b2[e];
        for (int e2 = 0; e2 < Ee; e2++) v += sh1[b][e2] * ctx_w2[e2 * Ee + e];
        scf[b][e] = v;
    }
    __syncthreads();
    if (tid < 32) {
        int b = tid >> 3, k = tid & 7;
        float v = gate_b2[0];
        for (int e = 0; e < Ee; e++) {
            float a = gate_b1[e];
            for (int i = 0; i < Ee; i++) a += lag_embed[k * Ee + i] * gate_w1[i * Ee + e];
            for (int i = 0; i < Ee; i++) a += scf[b][i] * gate_w1[(Ee + i) * Ee + e];
            v += gelu_exact(a) * gate_w2[e];
        }
        g_alpha[tid] = 1.0f / (1.0f + expf(-v));
    }
}

// ============================================================
// 2) A row normalization
// ============================================================
__global__ void k_normA(const float* __restrict__ A_list) {
    int row = blockIdx.x;
    int tid = threadIdx.x;
    float v = A_list[(size_t)row * Nn + tid];
    float s = v;
    #pragma unroll
    for (int off = 16; off > 0; off >>= 1) s += __shfl_xor_sync(0xFFFFFFFFu, s, off);
    __shared__ float wsum[8];
    if ((tid & 31) == 0) wsum[tid >> 5] = s;
    __syncthreads();
    float tot = 0.f;
    #pragma unroll
    for (int w = 0; w < 8; w++) tot += wsum[w];
    g_A[(size_t)row * Nn + tid] = v / fmaxf(tot, 1e-8f);
}

// ============================================================
// 2b) A -> bf16 with alpha folded.  grid (512, B), 256 thr
// ============================================================
__global__ void k_convA() {
    int b = blockIdx.y;
    int idx = blockIdx.x * 256 + threadIdx.x;           // 0..131071 float4s
    int k = idx >> 14;                                  // 16384 float4 per k
    float alpha = g_alpha[b * Kk + k];
    float4 v = ((const float4*)g_A)[idx];
    uint2 pk;
    pk.x = packbf2(v.x * alpha, v.y * alpha);
    pk.y = packbf2(v.z * alpha, v.w * alpha);
    *(uint2*)(g_Ab + (size_t)b * Kk * Nn * Nn + (size_t)idx * 4) = pk;
}

// ============================================================
// 2c) out_w transpose -> bf16 [h][f].  grid (256), 256 thr
// ============================================================
__global__ void k_owT(const float* __restrict__ out_w) {
    int h = blockIdx.x, f = threadIdx.x;
    g_owT[(size_t)h * Hh + f] = __float2bfloat16_rn(out_w[(size_t)f * Hh + h]);
}

// ============================================================
// 3) h_t = x @ in_w + in_b -> g_ht (B,T,N,H) fp32 + g_hbf (B,T,H,N) bf16
// grid (N/32, T, B), 256 threads. 4 rows per thread.
// ============================================================
__global__ void __launch_bounds__(256) k_ht(const float* __restrict__ x,
                                            const float* __restrict__ in_w,
                                            const float* __restrict__ in_b) {
    int n0 = blockIdx.x * 32, t = blockIdx.y, b = blockIdx.z;
    int tid = threadIdx.x;
    __shared__ float sx[32][Ff];
    __shared__ __nv_bfloat16 sbf[32][Hh + 8];
    for (int p = tid; p < 32 * Ff; p += 256) {
        int r = p >> 6, f = p & 63;
        sx[r][f] = x[(((size_t)b * Nn + n0 + r) * Tt + t) * Ff + f];
    }
    __syncthreads();
    int hq = tid & 31, rg = tid >> 5;
    u64 acc[4][4];
    {
        const ulonglong2* bb = (const ulonglong2*)in_b;
        ulonglong2 b01 = bb[hq * 2], b23 = bb[hq * 2 + 1];
        #pragma unroll
        for (int r = 0; r < 4; r++) {
            acc[r][0] = b01.x; acc[r][1] = b01.y; acc[r][2] = b23.x; acc[r][3] = b23.y;
        }
    }
    for (int f = 0; f < Ff; f++) {
        const ulonglong2* wr = (const ulonglong2*)(in_w + (size_t)f * Hh);
        ulonglong2 w01 = wr[hq * 2], w23 = wr[hq * 2 + 1];
        #pragma unroll
        for (int r = 0; r < 4; r++) {
            u64 ap = pk2(sx[4 * rg + r][f]);
            fma2(acc[r][0], ap, w01.x);
            fma2(acc[r][1], ap, w01.y);
            fma2(acc[r][2], ap, w23.x);
            fma2(acc[r][3], ap, w23.y);
        }
    }
    #pragma unroll
    for (int r = 0; r < 4; r++) {
        int row = 4 * rg + r;
        float* op = g_ht + (((size_t)b * Tt + t) * Nn + n0 + row) * Hh + hq * 8;
        ulonglong2 v0; v0.x = acc[r][0]; v0.y = acc[r][1];
        ulonglong2 v1; v1.x = acc[r][2]; v1.y = acc[r][3];
        *(ulonglong2*)(op)     = v0;
        *(ulonglong2*)(op + 4) = v1;
        #pragma unroll
        for (int c = 0; c < 4; c++) {
            float2 f2 = u2f(acc[r][c]);
            sbf[row][hq * 8 + c * 2 + 0] = __float2bfloat16_rn(f2.x);
            sbf[row][hq * 8 + c * 2 + 1] = __float2bfloat16_rn(f2.y);
        }
    }
    __syncthreads();
    {
        int h = tid;
        __nv_bfloat16* dst = g_hbf + (((size_t)b * Tt + t) * Hh + h) * Nn + n0;
        #pragma unroll
        for (int half = 0; half < 2; half++) {
            uint32_t o[8];
            #pragma unroll
            for (int q = 0; q < 8; q++) {
                __nv_bfloat162 pp;
                pp.x = sbf[half * 16 + 2 * q + 0][h];
                pp.y = sbf[half * 16 + 2 * q + 1][h];
                o[q] = *(uint32_t*)&pp;
            }
            *(uint4*)(dst + half * 16)     = make_uint4(o[0], o[1], o[2], o[3]);
            *(uint4*)(dst + half * 16 + 8) = make_uint4(o[4], o[5], o[6], o[7]);
        }
    }
}

// ============================================================
// 4) AGGREGATION, t-paired: CTA computes (i0,h0) 128x128 tiles for
//    t0 = 2*by and t1 = t0+1. Loop over lag-SOURCE tau: load B = h_bf[b,tau]
//    once; apply with A_{t1-tau} -> acc1 and A_{t0-tau} -> acc0.
// grid (4, T/2, B), 256 thr = 8 warps 2(m)x4(n), warp tile 64x32 per acc set.
// j-chunks of 128: steps = n_tau*2, double-buffered; 204KB smem, 1 CTA/SM.
// ============================================================
#define RB2   272                           /* 256B row + 16B pad */
#define AT_B  (128 * RB2)                   /* 34816 per tile */
#define PBUF  (3 * AT_B)                    /* [A0][A1][B] */
#define AGG_SMEM (2 * PBUF)                 /* 208896 */

__global__ void __launch_bounds__(256) k_agg() {
    extern __shared__ __align__(16) char smem[];
    uint32_t sbase = smem_u32(smem);
    int i0 = (blockIdx.x & 1) * 128;
    int h0 = (blockIdx.x >> 1) * 128;
    int t0 = blockIdx.y * 2, t1 = t0 + 1;
    int b  = blockIdx.z;
    int tid = threadIdx.x;
    int lane = tid & 31, wid = tid >> 5;
    int wm = wid & 1, wn = wid >> 1;

    int tau_lo = t0 - 7; if (tau_lo < 0) tau_lo = 0;
    int nsteps = (t1 - tau_lo + 1) * 2;

    // step s: tau = t1 - (s>>1), j0 = (s&1)*128
    // A1 slot (acc1) valid iff k1 = s>>1 <= 7; A0 slot valid iff 1 <= s>>1 <= 8
    auto load_step = [&](int s, int buf) {
        int kq = s >> 1;
        int tau = t1 - kq;
        int j0 = (s & 1) * 128;
        uint32_t base = sbase + buf * PBUF;
        const __nv_bfloat16* Bp = g_hbf + (((size_t)(b * Tt + tau) * Hh + h0) * Nn) + j0;
        #pragma unroll
        for (int u = tid; u < 2048; u += 256) {
            int r = u >> 4, c = u & 15;
            cpa16(base + 2 * AT_B + r * RB2 + c * 16, Bp + (size_t)r * Nn + c * 8);
        }
        if (kq <= 7) {                       // A1 = alpha*A_{k1}
            const __nv_bfloat16* Ap = g_Ab + (((size_t)(b * Kk + kq) * Nn + i0) * Nn) + j0;
            #pragma unroll
            for (int u = tid; u < 2048; u += 256) {
                int r = u >> 4, c = u & 15;
                cpa16(base + AT_B + r * RB2 + c * 16, Ap + (size_t)r * Nn + c * 8);
            }
        }
        if (kq >= 1 && kq <= 8) {            // A0 = alpha*A_{k0}, k0 = kq-1
            const __nv_bfloat16* Ap = g_Ab + (((size_t)(b * Kk + kq - 1) * Nn + i0) * Nn) + j0;
            #pragma unroll
            for (int u = tid; u < 2048; u += 256) {
                int r = u >> 4, c = u & 15;
                cpa16(base + r * RB2 + c * 16, Ap + (size_t)r * Nn + c * 8);
            }
        }
        CP_COMMIT();
    };

    float acc0[4][4][4], acc1[4][4][4];
    #pragma unroll
    for (int mi = 0; mi < 4; mi++)
        #pragma unroll
        for (int ni = 0; ni < 4; ni++)
            #pragma unroll
            for (int q = 0; q < 4; q++) { acc0[mi][ni][q] = 0.f; acc1[mi][ni][q] = 0.f; }

    load_step(0, 0);
    if (nsteps > 1) load_step(1, 1);

    uint32_t a_off = (uint32_t)(wm * 64 + (lane & 15)) * RB2 + (lane >> 4) * 16;
    uint32_t b_off = (uint32_t)(wn * 32 + ((lane >> 4) << 3) + (lane & 7)) * RB2
                   + ((lane >> 3) & 1) * 16;

    for (int s = 0; s < nsteps; s++) {
        int buf = s & 1;
        if (s + 1 < nsteps) { CP_WAIT1(); } else { CP_WAIT0(); }
        __syncthreads();
        int kq = s >> 1;
        bool v1 = (kq <= 7);
        bool v0 = (kq >= 1 && kq <= 8);
        uint32_t base = sbase + buf * PBUF;
        #pragma unroll
        for (int kk = 0; kk < 8; kk++) {
            uint32_t bfr[4][2];
            #pragma unroll
            for (int g = 0; g < 2; g++) {
                uint32_t r0, r1, r2, r3;
                ldsm_x4(r0, r1, r2, r3,
                        base + 2 * AT_B + b_off + (uint32_t)g * 16 * RB2 + kk * 32);
                bfr[g*2+0][0] = r0; bfr[g*2+0][1] = r1;
                bfr[g*2+1][0] = r2; bfr[g*2+1][1] = r3;
            }
            if (v1) {
                #pragma unroll
                for (int mi = 0; mi < 4; mi++) {
                    uint32_t a0, a1, a2, a3;
                    ldsm_x4(a0, a1, a2, a3,
                            base + AT_B + a_off + (uint32_t)mi * 16 * RB2 + kk * 32);
                    #pragma unroll
                    for (int ni = 0; ni < 4; ni++)
                        mma16816(acc1[mi][ni][0], acc1[mi][ni][1], acc1[mi][ni][2], acc1[mi][ni][3],
                                 a0, a1, a2, a3, bfr[ni][0], bfr[ni][1]);
                }
            }
            if (v0) {
                #pragma unroll
                for (int mi = 0; mi < 4; mi++) {
                    uint32_t a0, a1, a2, a3;
                    ldsm_x4(a0, a1, a2, a3,
                            base + a_off + (uint32_t)mi * 16 * RB2 + kk * 32);
                    #pragma unroll
                    for (int ni = 0; ni < 4; ni++)
                        mma16816(acc0[mi][ni][0], acc0[mi][ni][1], acc0[mi][ni][2], acc0[mi][ni][3],
                                 a0, a1, a2, a3, bfr[ni][0], bfr[ni][1]);
                }
            }
        }
        __syncthreads();
        if (s + 2 < nsteps) load_step(s + 2, buf);
    }

    // store bf16 mid for t0 and t1
    int rbase = i0 + wm * 64 + (lane >> 2);
    int cbase = h0 + wn * 32 + (lane & 3) * 2;
    __nv_bfloat16* ob0 = g_midbf + (((size_t)b * Tt + t0) * Nn) * Hh;
    __nv_bfloat16* ob1 = g_midbf + (((size_t)b * Tt + t1) * Nn) * Hh;
    #pragma unroll
    for (int mi = 0; mi < 4; mi++) {
        #pragma unroll
        for (int ni = 0; ni < 4; ni++) {
            int r = rbase + mi * 16;
            int c = cbase + ni * 8;
            *(uint32_t*)(ob0 + (size_t)r * Hh + c)       = packbf2(acc0[mi][ni][0], acc0[mi][ni][1]);
            *(uint32_t*)(ob0 + (size_t)(r + 8) * Hh + c) = packbf2(acc0[mi][ni][2], acc0[mi][ni][3]);
            *(uint32_t*)(ob1 + (size_t)r * Hh + c)       = packbf2(acc1[mi][ni][0], acc1[mi][ni][1]);
            *(uint32_t*)(ob1 + (size_t)(r + 8) * Hh + c) = packbf2(acc1[mi][ni][2], acc1[mi][ni][3]);
        }
    }
}

// ============================================================
// 5) EPILOGUE via mma.sync: out = midbf @ owT^T + out_b; residual(g_ht fp32);
//    LN; gelu; transposed store.  (unchanged from R10)
// ============================================================
#define ROW_B 144
#define EA_B (64 * ROW_B)
#define EB_B (256 * ROW_B)
#define EBUF (EA_B + EB_B)
#define RES_ST 264
#define EPI_SMEM (2 * EBUF)

__global__ void __launch_bounds__(256) k_epi(const float* __restrict__ out_b,
                                             const float* __restrict__ ln_g,
                                             const float* __restrict__ ln_b,
                                             float* __restrict__ out) {
    extern __shared__ __align__(16) char smem[];
    uint32_t sbase = smem_u32(smem);
    float* resf = (float*)smem;
    int n0 = blockIdx.x * 64, t = blockIdx.y, b = blockIdx.z;
    int tid = threadIdx.x;
    int lane = tid & 31, wid = tid >> 5;
    int wm = wid & 1, wn = wid >> 1;

    auto load_chunk = [&](int ch, int buf) {
        int f0 = ch * 64;
        const __nv_bfloat16* Ap = g_midbf + (((size_t)b * Tt + t) * Nn + n0) * Hh + f0;
        const __nv_bfloat16* Bp = g_owT + f0;
        uint32_t Ad = sbase + buf * EBUF;
        uint32_t Bd = Ad + EA_B;
        #pragma unroll
        for (int u = tid; u < 512; u += 256) {
            int r = u >> 3, c = u & 7;
            cpa16(Ad + r * ROW_B + c * 16, Ap + (size_t)r * Hh + c * 8);
        }
        #pragma unroll
        for (int u = tid; u < 2048; u += 256) {
            int r = u >> 3, c = u & 7;
            cpa16(Bd + r * ROW_B + c * 16, Bp + (size_t)r * Hh + c * 8);
        }
        CP_COMMIT();
    };

    float acc[2][8][4];
    #pragma unroll
    for (int mi = 0; mi < 2; mi++)
        #pragma unroll
        for (int ni = 0; ni < 8; ni++)
            #pragma unroll
            for (int q = 0; q < 4; q++) acc[mi][ni][q] = 0.f;

    load_chunk(0, 0);
    load_chunk(1, 1);

    uint32_t a_off = (uint32_t)(wm * 32 + (lane & 15)) * ROW_B + (lane >> 4) * 16;
    uint32_t b_off = (uint32_t)(wn * 64 + ((lane >> 4) << 3) + (lane & 7)) * ROW_B
                   + ((lane >> 3) & 1) * 16;

    #pragma unroll
    for (int ch = 0; ch < 4; ch++) {
        int buf = ch & 1;
        if (ch + 1 < 4) { CP_WAIT1(); } else { CP_WAIT0(); }
        __syncthreads();
        uint32_t Ad = sbase + buf * EBUF;
        uint32_t Bd = Ad + EA_B;
        #pragma unroll
        for (int kk = 0; kk < 4; kk++) {
            uint32_t a[2][4];
            #pragma unroll
            for (int mi = 0; mi < 2; mi++)
                ldsm_x4(a[mi][0], a[mi][1], a[mi][2], a[mi][3],
                        Ad + a_off + (uint32_t)mi * 16 * ROW_B + kk * 32);
            uint32_t bfr[8][2];
            #pragma unroll
            for (int g = 0; g < 4; g++) {
                uint32_t r0, r1, r2, r3;
                ldsm_x4(r0, r1, r2, r3,
                        Bd + b_off + (uint32_t)g * 16 * ROW_B + kk * 32);
                bfr[g*2+0][0] = r0; bfr[g*2+0][1] = r1;
                bfr[g*2+1][0] = r2; bfr[g*2+1][1] = r3;
            }
            #pragma unroll
            for (int mi = 0; mi < 2; mi++)
                #pragma unroll
                for (int ni = 0; ni < 8; ni++)
                    mma16816(acc[mi][ni][0], acc[mi][ni][1], acc[mi][ni][2], acc[mi][ni][3],
                             a[mi][0], a[mi][1], a[mi][2], a[mi][3],
                             bfr[ni][0], bfr[ni][1]);
        }
        __syncthreads();
        if (ch + 2 < 4) load_chunk(ch + 2, buf);
    }

    {
        int rb = wm * 32 + (lane >> 2);
        int cb = wn * 64 + (lane & 3) * 2;
        #pragma unroll
        for (int mi = 0; mi < 2; mi++) {
            #pragma unroll
            for (int ni = 0; ni < 8; ni++) {
                int r = rb + mi * 16;
                int c = cb + ni * 8;
                float b0 = out_b[c], b1 = out_b[c + 1];
                resf[(size_t)r * RES_ST + c]           = acc[mi][ni][0] + b0;
                resf[(size_t)r * RES_ST + c + 1]       = acc[mi][ni][1] + b1;
                resf[(size_t)(r + 8) * RES_ST + c]     = acc[mi][ni][2] + b0;
                resf[(size_t)(r + 8) * RES_ST + c + 1] = acc[mi][ni][3] + b1;
            }
        }
    }
    __syncthreads();

    const float* hb = g_ht + (((size_t)b * Tt + t) * Nn + n0) * Hh;
    #pragma unroll
    for (int rr = 0; rr < 8; rr++) {
        int row = wid * 8 + rr;
        float v[8];
        float s = 0.f, s2 = 0.f;
        const float4* hrow = (const float4*)(hb + (size_t)row * Hh);
        float4 h0 = hrow[lane * 2], h1 = hrow[lane * 2 + 1];
        v[0] = resf[(size_t)row * RES_ST + lane * 8 + 0] + h0.x;
        v[1] = resf[(size_t)row * RES_ST + lane * 8 + 1] + h0.y;
        v[2] = resf[(size_t)row * RES_ST + lane * 8 + 2] + h0.z;
        v[3] = resf[(size_t)row * RES_ST + lane * 8 + 3] + h0.w;
        v[4] = resf[(size_t)row * RES_ST + lane * 8 + 4] + h1.x;
        v[5] = resf[(size_t)row * RES_ST + lane * 8 + 5] + h1.y;
        v[6] = resf[(size_t)row * RES_ST + lane * 8 + 6] + h1.z;
        v[7] = resf[(size_t)row * RES_ST + lane * 8 + 7] + h1.w;
        #pragma unroll
        for (int q = 0; q < 8; q++) { s += v[q]; s2 += v[q] * v[q]; }
        #pragma unroll
        for (int off = 16; off > 0; off >>= 1) {
            s  += __shfl_xor_sync(0xFFFFFFFFu, s,  off);
            s2 += __shfl_xor_sync(0xFFFFFFFFu, s2, off);
        }
        float mu  = s * (1.0f / Hh);
        float var = s2 * (1.0f / Hh) - mu * mu;
        float rstd = rsqrtf(var + 1e-5f);
        float* op = out + (((size_t)b * Nn + n0 + row) * Tt + t) * Hh + lane * 8;
        #pragma unroll
        for (int q = 0; q < 8; q += 4) {
            float4 o;
            float y0 = (v[q+0] - mu) * rstd * ln_g[lane*8+q+0] + ln_b[lane*8+q+0];
            float y1 = (v[q+1] - mu) * rstd * ln_g[lane*8+q+1] + ln_b[lane*8+q+1];
            float y2 = (v[q+2] - mu) * rstd * ln_g[lane*8+q+2] + ln_b[lane*8+q+2];
            float y3 = (v[q+3] - mu) * rstd * ln_g[lane*8+q+3] + ln_b[lane*8+q+3];
            o.x = gelu_exact(y0); o.y = gelu_exact(y1);
            o.z = gelu_exact(y2); o.w = gelu_exact(y3);
            *(float4*)(op + q) = o;
        }
    }
}

// ============================================================
extern "C" void kernel_launch(void* const* d_in, const int* in_sizes, int n_in,
                              void* d_out, int out_size) {
    const float* x      = (const float*)d_in[0];
    const float* A_list = (const float*)d_in[1];
    const float* in_w   = (const float*)d_in[2];
    const float* in_b   = (const float*)d_in[3];
    const float* out_w  = (const float*)d_in[4];
    const float* out_b  = (const float*)d_in[5];
    const float* lag    = (const float*)d_in[6];
    const float* cw1    = (const float*)d_in[7];
    const float* cb1    = (const float*)d_in[8];
    const float* cw2    = (const float*)d_in[9];
    const float* cb2    = (const float*)d_in[10];
    const float* gw1    = (const float*)d_in[11];
    const float* gb1    = (const float*)d_in[12];
    const float* gw2    = (const float*)d_in[13];
    const float* gb2    = (const float*)d_in[14];
    const float* lng    = (const float*)d_in[15];
    const float* lnb    = (const float*)d_in[16];
    float* out = (float*)d_out;

    cudaFuncSetAttribute(k_agg, cudaFuncAttributeMaxDynamicSharedMemorySize, AGG_SMEM);
    cudaFuncSetAttribute(k_epi, cudaFuncAttributeMaxDynamicSharedMemorySize, EPI_SMEM);

    k_ctx_partial<<<dim3(32, Bb), 256>>>(x);
    k_small<<<1, 64>>>(lag, cw1, cb1, cw2, cb2, gw1, gb1, gw2, gb2);
    k_normA<<<Kk * Nn, 256>>>(A_list);
    k_convA<<<dim3(512, Bb), 256>>>();
    k_owT<<<256, 256>>>(out_w);
    k_ht<<<dim3(Nn / 32, Tt, Bb), 256>>>(x, in_w, in_b);
    k_agg<<<dim3(4, Tt / 2, Bb), 256, AGG_SMEM>>>();
    k_epi<<<dim3(Nn / 64, Tt, Bb), 256, EPI_SMEM>>>(out_b, lng, lnb, out);
}

// round 13
// speedup vs baseline: 1.0224x; 1.0224x over previous
#include <cuda_runtime.h>
#include <cuda_bf16.h>
#include <math.h>
#include <stdint.h>

#define Bb 4
#define Nn 256
#define Tt 128
#define Ff 64
#define Kk 8
#define Hh 256
#define Ee 8

// ---- scratch (static __device__ per allocation rules) ----
__device__ __align__(16) float g_ht [Bb*Tt*Nn*Hh];            // h (B,T,N,H) fp32
__device__ __align__(16) float g_A  [Kk*Nn*Nn];               // row-normalized A
__device__ __align__(16) __nv_bfloat16 g_Ab [Bb*Kk*Nn*Nn];    // bf16 alpha*A (row-major i x j)
__device__ __align__(16) __nv_bfloat16 g_hbf[Bb*Tt*Hh*Nn];    // bf16 h transposed (B,T,H,N)
__device__ __align__(16) __nv_bfloat16 g_midbf[Bb*Tt*Nn*Hh];  // bf16 aggregation result (B,T,N,H)
__device__ __align__(16) __nv_bfloat16 g_owT[Hh*Hh];          // bf16 out_w transposed [h][f]
__device__             float g_ctxp[Bb*32*Ff];
__device__             float g_alpha[Bb*Kk];

typedef unsigned long long u64;

__device__ __forceinline__ u64 pk2(float x) {
    u64 r; asm("mov.b64 %0, {%1, %1};" : "=l"(r) : "f"(x)); return r;
}
__device__ __forceinline__ void fma2(u64 &d, u64 a, u64 b) {
    asm("fma.rn.f32x2 %0, %1, %2, %0;" : "+l"(d) : "l"(a), "l"(b));
}
__device__ __forceinline__ float2 u2f(u64 v) {
    float2 f; asm("mov.b64 {%0, %1}, %2;" : "=f"(f.x), "=f"(f.y) : "l"(v)); return f;
}
__device__ __forceinline__ float gelu_exact(float v) {
    return 0.5f * v * (1.0f + erff(v * 0.70710678118654752f));
}
__device__ __forceinline__ uint32_t smem_u32(const void* p) {
    uint32_t a; asm("{ .reg .u64 t; cvta.to.shared.u64 t, %1; cvt.u32.u64 %0, t; }" : "=r"(a) : "l"(p));
    return a;
}
__device__ __forceinline__ void cpa16(uint32_t dst, const void* src) {
    asm volatile("cp.async.cg.shared.global [%0], [%1], 16;" :: "r"(dst), "l"(src));
}
#define CP_COMMIT()  asm volatile("cp.async.commit_group;" ::: "memory")
#define CP_WAIT2()   asm volatile("cp.async.wait_group 2;" ::: "memory")
#define CP_WAIT1()   asm volatile("cp.async.wait_group 1;" ::: "memory")
#define CP_WAIT0()   asm volatile("cp.async.wait_group 0;" ::: "memory")

__device__ __forceinline__ void ldsm_x4(uint32_t &r0, uint32_t &r1, uint32_t &r2, uint32_t &r3,
                                        uint32_t addr) {
    asm volatile("ldmatrix.sync.aligned.m8n8.x4.shared.b16 {%0,%1,%2,%3}, [%4];"
                 : "=r"(r0), "=r"(r1), "=r"(r2), "=r"(r3) : "r"(addr));
}
__device__ __forceinline__ void mma16816(float &c0, float &c1, float &c2, float &c3,
                                         uint32_t a0, uint32_t a1, uint32_t a2, uint32_t a3,
                                         uint32_t b0, uint32_t b1) {
    asm volatile("mma.sync.aligned.m16n8k16.row.col.f32.bf16.bf16.f32 "
                 "{%0,%1,%2,%3}, {%4,%5,%6,%7}, {%8,%9}, {%0,%1,%2,%3};"
                 : "+f"(c0), "+f"(c1), "+f"(c2), "+f"(c3)
                 : "r"(a0), "r"(a1), "r"(a2), "r"(a3), "r"(b0), "r"(b1));
}
__device__ __forceinline__ uint32_t packbf2(float x, float y) {
    __nv_bfloat162 p = __floats2bfloat162_rn(x, y);
    return *(uint32_t*)&p;
}

// ============================================================
// 1a) ctx partial sums
// ============================================================
__global__ void k_ctx_partial(const float* __restrict__ x) {
    int b = blockIdx.y, g = blockIdx.x;
    int tid = threadIdx.x;
    int fg = tid & 15, r = tid >> 4;
    const float4* xp = (const float4*)(x + (size_t)b * Nn * Tt * Ff);
    float4 s = make_float4(0.f, 0.f, 0.f, 0.f);
    int base = g * 1024;
    for (int idx = base + r; idx < base + 1024; idx += 16) {
        float4 v = xp[idx * 16 + fg];
        s.x += v.x; s.y += v.y; s.z += v.z; s.w += v.w;
    }
    __shared__ float sp[16][64];
    sp[r][fg*4+0] = s.x; sp[r][fg*4+1] = s.y; sp[r][fg*4+2] = s.z; sp[r][fg*4+3] = s.w;
    __syncthreads();
    if (tid < 64) {
        float acc = 0.f;
        #pragma unroll
        for (int rr = 0; rr < 16; rr++) acc += sp[rr][tid];
        g_ctxp[(b * 32 + g) * 64 + tid] = acc;
    }
}

// ============================================================
// 1b) ctx finish + gate MLP + alpha
// ============================================================
__global__ void k_small(const float* __restrict__ lag_embed,
                        const float* __restrict__ ctx_w1, const float* __restrict__ ctx_b1,
                        const float* __restrict__ ctx_w2, const float* __restrict__ ctx_b2,
                        const float* __restrict__ gate_w1, const float* __restrict__ gate_b1,
                        const float* __restrict__ gate_w2, const float* __restrict__ gate_b2) {
    __shared__ float sctx[Bb][Ff];
    __shared__ float sh1[Bb][Ee];
    __shared__ float scf[Bb][Ee];
    int tid = threadIdx.x;
    for (int p = tid; p < Bb * Ff; p += 64) {
        int b = p >> 6, f = p & 63;
        float s = 0.f;
        for (int g = 0; g < 32; g++) s += g_ctxp[(b * 32 + g) * 64 + f];
        sctx[b][f] = s * (1.0f / (Nn * Tt));
    }
    __syncthreads();
    if (tid < 32) {
        int b = tid >> 3, e = tid & 7;
        float v = ctx_b1[e];
        for (int f = 0; f < Ff; f++) v += sctx[b][f] * ctx_w1[f * Ee + e];
        sh1[b][e] = gelu_exact(v);
    }
    __syncthreads();
    if (tid < 32) {
        int b = tid >> 3, e = tid & 7;
        float v = ctx_b2[e];
        for (int e2 = 0; e2 < Ee; e2++) v += sh1[b][e2] * ctx_w2[e2 * Ee + e];
        scf[b][e] = v;
    }
    __syncthreads();
    if (tid < 32) {
        int b = tid >> 3, k = tid & 7;
        float v = gate_b2[0];
        for (int e = 0; e < Ee; e++) {
            float a = gate_b1[e];
            for (int i = 0; i < Ee; i++) a += lag_embed[k * Ee + i] * gate_w1[i * Ee + e];
            for (int i = 0; i < Ee; i++) a += scf[b][i] * gate_w1[(Ee + i) * Ee + e];
            v += gelu_exact(a) * gate_w2[e];
        }
        g_alpha[tid] = 1.0f / (1.0f + expf(-v));
    }
}

// ============================================================
// 2) A row normalization
// ============================================================
__global__ void k_normA(const float* __restrict__ A_list) {
    int row = blockIdx.x;
    int tid = threadIdx.x;
    float v = A_list[(size_t)row * Nn + tid];
    float s = v;
    #pragma unroll
    for (int off = 16; off > 0; off >>= 1) s += __shfl_xor_sync(0xFFFFFFFFu, s, off);
    __shared__ float wsum[8];
    if ((tid & 31) == 0) wsum[tid >> 5] = s;
    __syncthreads();
    float tot = 0.f;
    #pragma unroll
    for (int w = 0; w < 8; w++) tot += wsum[w];
    g_A[(size_t)row * Nn + tid] = v / fmaxf(tot, 1e-8f);
}

// ============================================================
// 2b) A -> bf16 with alpha folded.  grid (512, B), 256 thr
// ============================================================
__global__ void k_convA() {
    int b = blockIdx.y;
    int idx = blockIdx.x * 256 + threadIdx.x;           // 0..131071 float4s
    int k = idx >> 14;                                  // 16384 float4 per k
    float alpha = g_alpha[b * Kk + k];
    float4 v = ((const float4*)g_A)[idx];
    uint2 pk;
    pk.x = packbf2(v.x * alpha, v.y * alpha);
    pk.y = packbf2(v.z * alpha, v.w * alpha);
    *(uint2*)(g_Ab + (size_t)b * Kk * Nn * Nn + (size_t)idx * 4) = pk;
}

// ============================================================
// 2c) out_w transpose -> bf16 [h][f].  grid (256), 256 thr
// ============================================================
__global__ void k_owT(const float* __restrict__ out_w) {
    int h = blockIdx.x, f = threadIdx.x;
    g_owT[(size_t)h * Hh + f] = __float2bfloat16_rn(out_w[(size_t)f * Hh + h]);
}

// ============================================================
// 3) h_t = x @ in_w + in_b -> g_ht (B,T,N,H) fp32 + g_hbf (B,T,H,N) bf16
// grid (N/32, T, B), 256 threads. 4 rows per thread.
// ============================================================
__global__ void __launch_bounds__(256) k_ht(const float* __restrict__ x,
                                            const float* __restrict__ in_w,
                                            const float* __restrict__ in_b) {
    int n0 = blockIdx.x * 32, t = blockIdx.y, b = blockIdx.z;
    int tid = threadIdx.x;
    __shared__ float sx[32][Ff];
    __shared__ __nv_bfloat16 sbf[32][Hh + 8];
    for (int p = tid; p < 32 * Ff; p += 256) {
        int r = p >> 6, f = p & 63;
        sx[r][f] = x[(((size_t)b * Nn + n0 + r) * Tt + t) * Ff + f];
    }
    __syncthreads();
    int hq = tid & 31, rg = tid >> 5;
    u64 acc[4][4];
    {
        const ulonglong2* bb = (const ulonglong2*)in_b;
        ulonglong2 b01 = bb[hq * 2], b23 = bb[hq * 2 + 1];
        #pragma unroll
        for (int r = 0; r < 4; r++) {
            acc[r][0] = b01.x; acc[r][1] = b01.y; acc[r][2] = b23.x; acc[r][3] = b23.y;
        }
    }
    for (int f = 0; f < Ff; f++) {
        const ulonglong2* wr = (const ulonglong2*)(in_w + (size_t)f * Hh);
        ulonglong2 w01 = wr[hq * 2], w23 = wr[hq * 2 + 1];
        #pragma unroll
        for (int r = 0; r < 4; r++) {
            u64 ap = pk2(sx[4 * rg + r][f]);
            fma2(acc[r][0], ap, w01.x);
            fma2(acc[r][1], ap, w01.y);
            fma2(acc[r][2], ap, w23.x);
            fma2(acc[r][3], ap, w23.y);
        }
    }
    #pragma unroll
    for (int r = 0; r < 4; r++) {
        int row = 4 * rg + r;
        float* op = g_ht + (((size_t)b * Tt + t) * Nn + n0 + row) * Hh + hq * 8;
        ulonglong2 v0; v0.x = acc[r][0]; v0.y = acc[r][1];
        ulonglong2 v1; v1.x = acc[r][2]; v1.y = acc[r][3];
        *(ulonglong2*)(op)     = v0;
        *(ulonglong2*)(op + 4) = v1;
        #pragma unroll
        for (int c = 0; c < 4; c++) {
            float2 f2 = u2f(acc[r][c]);
            sbf[row][hq * 8 + c * 2 + 0] = __float2bfloat16_rn(f2.x);
            sbf[row][hq * 8 + c * 2 + 1] = __float2bfloat16_rn(f2.y);
        }
    }
    __syncthreads();
    {
        int h = tid;
        __nv_bfloat16* dst = g_hbf + (((size_t)b * Tt + t) * Hh + h) * Nn + n0;
        #pragma unroll
        for (int half = 0; half < 2; half++) {
            uint32_t o[8];
            #pragma unroll
            for (int q = 0; q < 8; q++) {
                __nv_bfloat162 pp;
                pp.x = sbf[half * 16 + 2 * q + 0][h];
                pp.y = sbf[half * 16 + 2 * q + 1][h];
                o[q] = *(uint32_t*)&pp;
            }
            *(uint4*)(dst + half * 16)     = make_uint4(o[0], o[1], o[2], o[3]);
            *(uint4*)(dst + half * 16 + 8) = make_uint4(o[4], o[5], o[6], o[7]);
        }
    }
}

// ============================================================
// 4) AGGREGATION via mma.sync (R10 structure + 3-stage pipeline):
//    midbf[b,t,i,h] = bf16( sum_k (alpha A_k)[i,:] @ h_bf[b,t-k][:,h] )
// grid (4, T, B): blockIdx.x = i-tile(0..1) | h-tile(0..1)<<1
// 256 threads = 8 warps in 2(m) x 4(n); warp tile 64 x 32.  2 CTAs/SM.
// ============================================================
#define ROW_B 144                          /* padded row stride in bytes */
#define TILE_B (128 * ROW_B)
#define ABUF   (2 * TILE_B)                /* A + B per stage = 36864 */
#define NSTAGE 3
#define AGG_SMEM (NSTAGE * ABUF)           /* 110592 */

__global__ void __launch_bounds__(256, 2) k_agg() {
    extern __shared__ __align__(16) char smem[];
    uint32_t sbase = smem_u32(smem);
    int i0 = (blockIdx.x & 1) * 128;
    int h0 = (blockIdx.x >> 1) * 128;
    int t  = blockIdx.y;
    int b  = blockIdx.z;
    int tid = threadIdx.x;
    int lane = tid & 31, wid = tid >> 5;
    int wm = wid & 1, wn = wid >> 1;

    int kmax = (t + 1 < Kk) ? (t + 1) : Kk;
    int steps = kmax * 4;

    auto load_chunk = [&](int s, int buf) {
        int k = s >> 2, j0 = (s & 3) * 64;
        const __nv_bfloat16* Ap = g_Ab + (((size_t)(b * Kk + k) * Nn + i0) * Nn) + j0;
        const __nv_bfloat16* Hp = g_hbf + (((size_t)(b * Tt + (t - k)) * Hh + h0) * Nn) + j0;
        uint32_t Ad = sbase + buf * ABUF;
        uint32_t Bd = Ad + TILE_B;
        #pragma unroll
        for (int u = tid; u < 1024; u += 256) {
            int r = u >> 3, c = u & 7;
            cpa16(Ad + r * ROW_B + c * 16, Ap + (size_t)r * Nn + c * 8);
        }
        #pragma unroll
        for (int u = tid; u < 1024; u += 256) {
            int r = u >> 3, c = u & 7;
            cpa16(Bd + r * ROW_B + c * 16, Hp + (size_t)r * Nn + c * 8);
        }
        CP_COMMIT();
    };

    float acc[4][4][4];
    #pragma unroll
    for (int mi = 0; mi < 4; mi++)
        #pragma unroll
        for (int ni = 0; ni < 4; ni++)
            #pragma unroll
            for (int q = 0; q < 4; q++) acc[mi][ni][q] = 0.f;

    int issued = 0;
    #pragma unroll
    for (int p = 0; p < NSTAGE; p++) {
        if (p < steps) { load_chunk(p, p); issued++; }
    }

    uint32_t a_off = (uint32_t)(wm * 64 + (lane & 15)) * ROW_B + (lane >> 4) * 16;
    uint32_t b_off = (uint32_t)(wn * 32 + ((lane >> 4) << 3) + (lane & 7)) * ROW_B
                   + ((lane >> 3) & 1) * 16;

    for (int s = 0; s < steps; s++) {
        int buf = s % NSTAGE;
        int rem = issued - s - 1;
        if (rem >= 2) { CP_WAIT2(); } else if (rem == 1) { CP_WAIT1(); } else { CP_WAIT0(); }
        __syncthreads();
        uint32_t Ad = sbase + buf * ABUF;
        uint32_t Bd = Ad + TILE_B;
        #pragma unroll
        for (int kk = 0; kk < 4; kk++) {
            uint32_t a[4][4];
            #pragma unroll
            for (int mi = 0; mi < 4; mi++)
                ldsm_x4(a[mi][0], a[mi][1], a[mi][2], a[mi][3],
                        Ad + a_off + (uint32_t)mi * 16 * ROW_B + kk * 32);
            uint32_t bfr[4][2];
            #pragma unroll
            for (int g = 0; g < 2; g++) {
                uint32_t r0, r1, r2, r3;
                ldsm_x4(r0, r1, r2, r3,
                        Bd + b_off + (uint32_t)g * 16 * ROW_B + kk * 32);
                bfr[g*2+0][0] = r0; bfr[g*2+0][1] = r1;
                bfr[g*2+1][0] = r2; bfr[g*2+1][1] = r3;
            }
            #pragma unroll
            for (int mi = 0; mi < 4; mi++)
                #pragma unroll
                for (int ni = 0; ni < 4; ni++)
                    mma16816(acc[mi][ni][0], acc[mi][ni][1], acc[mi][ni][2], acc[mi][ni][3],
                             a[mi][0], a[mi][1], a[mi][2], a[mi][3],
                             bfr[ni][0], bfr[ni][1]);
        }
        __syncthreads();
        if (issued < steps) { load_chunk(issued, issued % NSTAGE); issued++; }
    }

    // store bf16 mid
    __nv_bfloat16* ob = g_midbf + (((size_t)b * Tt + t) * Nn) * Hh;
    int rbase = i0 + wm * 64 + (lane >> 2);
    int cbase = h0 + wn * 32 + (lane & 3) * 2;
    #pragma unroll
    for (int mi = 0; mi < 4; mi++) {
        #pragma unroll
        for (int ni = 0; ni < 4; ni++) {
            int r = rbase + mi * 16;
            int c = cbase + ni * 8;
            *(uint32_t*)(ob + (size_t)r * Hh + c)       = packbf2(acc[mi][ni][0], acc[mi][ni][1]);
            *(uint32_t*)(ob + (size_t)(r + 8) * Hh + c) = packbf2(acc[mi][ni][2], acc[mi][ni][3]);
        }
    }
}

// ============================================================
// 5) EPILOGUE via mma.sync: out = midbf @ owT^T + out_b; residual(g_ht fp32);
//    LN; gelu; transposed store.  (unchanged from R10)
// ============================================================
#define EA_B (64 * ROW_B)                  /* 9216  */
#define EB_B (256 * ROW_B)                 /* 36864 */
#define EBUF (EA_B + EB_B)                 /* 46080 */
#define RES_ST 264                         /* fp32 res row stride (words) */
#define EPI_SMEM (2 * EBUF)                /* 92160 */

__global__ void __launch_bounds__(256) k_epi(const float* __restrict__ out_b,
                                             const float* __restrict__ ln_g,
                                             const float* __restrict__ ln_b,
                                             float* __restrict__ out) {
    extern __shared__ __align__(16) char smem[];
    uint32_t sbase = smem_u32(smem);
    float* resf = (float*)smem;
    int n0 = blockIdx.x * 64, t = blockIdx.y, b = blockIdx.z;
    int tid = threadIdx.x;
    int lane = tid & 31, wid = tid >> 5;
    int wm = wid & 1, wn = wid >> 1;

    auto load_chunk = [&](int ch, int buf) {
        int f0 = ch * 64;
        const __nv_bfloat16* Ap = g_midbf + (((size_t)b * Tt + t) * Nn + n0) * Hh + f0;
        const __nv_bfloat16* Bp = g_owT + f0;
        uint32_t Ad = sbase + buf * EBUF;
        uint32_t Bd = Ad + EA_B;
        #pragma unroll
        for (int u = tid; u < 512; u += 256) {
            int r = u >> 3, c = u & 7;
            cpa16(Ad + r * ROW_B + c * 16, Ap + (size_t)r * Hh + c * 8);
        }
        #pragma unroll
        for (int u = tid; u < 2048; u += 256) {
            int r = u >> 3, c = u & 7;
            cpa16(Bd + r * ROW_B + c * 16, Bp + (size_t)r * Hh + c * 8);
        }
        CP_COMMIT();
    };

    float acc[2][8][4];
    #pragma unroll
    for (int mi = 0; mi < 2; mi++)
        #pragma unroll
        for (int ni = 0; ni < 8; ni++)
            #pragma unroll
            for (int q = 0; q < 4; q++) acc[mi][ni][q] = 0.f;

    load_chunk(0, 0);
    load_chunk(1, 1);

    uint32_t a_off = (uint32_t)(wm * 32 + (lane & 15)) * ROW_B + (lane >> 4) * 16;
    uint32_t b_off = (uint32_t)(wn * 64 + ((lane >> 4) << 3) + (lane & 7)) * ROW_B
                   + ((lane >> 3) & 1) * 16;

    #pragma unroll
    for (int ch = 0; ch < 4; ch++) {
        int buf = ch & 1;
        if (ch + 1 < 4) { CP_WAIT1(); } else { CP_WAIT0(); }
        __syncthreads();
        uint32_t Ad = sbase + buf * EBUF;
        uint32_t Bd = Ad + EA_B;
        #pragma unroll
        for (int kk = 0; kk < 4; kk++) {
            uint32_t a[2][4];
            #pragma unroll
            for (int mi = 0; mi < 2; mi++)
                ldsm_x4(a[mi][0], a[mi][1], a[mi][2], a[mi][3],
                        Ad + a_off + (uint32_t)mi * 16 * ROW_B + kk * 32);
            uint32_t bfr[8][2];
            #pragma unroll
            for (int g = 0; g < 4; g++) {
                uint32_t r0, r1, r2, r3;
                ldsm_x4(r0, r1, r2, r3,
                        Bd + b_off + (uint32_t)g * 16 * ROW_B + kk * 32);
                bfr[g*2+0][0] = r0; bfr[g*2+0][1] = r1;
                bfr[g*2+1][0] = r2; bfr[g*2+1][1] = r3;
            }
            #pragma unroll
            for (int mi = 0; mi < 2; mi++)
                #pragma unroll
                for (int ni = 0; ni < 8; ni++)
                    mma16816(acc[mi][ni][0], acc[mi][ni][1], acc[mi][ni][2], acc[mi][ni][3],
                             a[mi][0], a[mi][1], a[mi][2], a[mi][3],
                             bfr[ni][0], bfr[ni][1]);
        }
        __syncthreads();
        if (ch + 2 < 4) load_chunk(ch + 2, buf);
    }

    {
        int rb = wm * 32 + (lane >> 2);
        int cb = wn * 64 + (lane & 3) * 2;
        #pragma unroll
        for (int mi = 0; mi < 2; mi++) {
            #pragma unroll
            for (int ni = 0; ni < 8; ni++) {
                int r = rb + mi * 16;
                int c = cb + ni * 8;
                float b0 = out_b[c], b1 = out_b[c + 1];
                resf[(size_t)r * RES_ST + c]           = acc[mi][ni][0] + b0;
                resf[(size_t)r * RES_ST + c + 1]       = acc[mi][ni][1] + b1;
                resf[(size_t)(r + 8) * RES_ST + c]     = acc[mi][ni][2] + b0;
                resf[(size_t)(r + 8) * RES_ST + c + 1] = acc[mi][ni][3] + b1;
            }
        }
    }
    __syncthreads();

    const float* hb = g_ht + (((size_t)b * Tt + t) * Nn + n0) * Hh;
    #pragma unroll
    for (int rr = 0; rr < 8; rr++) {
        int row = wid * 8 + rr;
        float v[8];
        float s = 0.f, s2 = 0.f;
        const float4* hrow = (const float4*)(hb + (size_t)row * Hh);
        float4 h0 = hrow[lane * 2], h1 = hrow[lane * 2 + 1];
        v[0] = resf[(size_t)row * RES_ST + lane * 8 + 0] + h0.x;
        v[1] = resf[(size_t)row * RES_ST + lane * 8 + 1] + h0.y;
        v[2] = resf[(size_t)row * RES_ST + lane * 8 + 2] + h0.z;
        v[3] = resf[(size_t)row * RES_ST + lane * 8 + 3] + h0.w;
        v[4] = resf[(size_t)row * RES_ST + lane * 8 + 4] + h1.x;
        v[5] = resf[(size_t)row * RES_ST + lane * 8 + 5] + h1.y;
        v[6] = resf[(size_t)row * RES_ST + lane * 8 + 6] + h1.z;
        v[7] = resf[(size_t)row * RES_ST + lane * 8 + 7] + h1.w;
        #pragma unroll
        for (int q = 0; q < 8; q++) { s += v[q]; s2 += v[q] * v[q]; }
        #pragma unroll
        for (int off = 16; off > 0; off >>= 1) {
            s  += __shfl_xor_sync(0xFFFFFFFFu, s,  off);
            s2 += __shfl_xor_sync(0xFFFFFFFFu, s2, off);
        }
        float mu  = s * (1.0f / Hh);
        float var = s2 * (1.0f / Hh) - mu * mu;
        float rstd = rsqrtf(var + 1e-5f);
        float* op = out + (((size_t)b * Nn + n0 + row) * Tt + t) * Hh + lane * 8;
        #pragma unroll
        for (int q = 0; q < 8; q += 4) {
            float4 o;
            float y0 = (v[q+0] - mu) * rstd * ln_g[lane*8+q+0] + ln_b[lane*8+q+0];
            float y1 = (v[q+1] - mu) * rstd * ln_g[lane*8+q+1] + ln_b[lane*8+q+1];
            float y2 = (v[q+2] - mu) * rstd * ln_g[lane*8+q+2] + ln_b[lane*8+q+2];
            float y3 = (v[q+3] - mu) * rstd * ln_g[lane*8+q+3] + ln_b[lane*8+q+3];
            o.x = gelu_exact(y0); o.y = gelu_exact(y1);
            o.z = gelu_exact(y2); o.w = gelu_exact(y3);
            *(float4*)(op + q) = o;
        }
    }
}

// ============================================================
extern "C" void kernel_launch(void* const* d_in, const int* in_sizes, int n_in,
                              void* d_out, int out_size) {
    const float* x      = (const float*)d_in[0];
    const float* A_list = (const float*)d_in[1];
    const float* in_w   = (const float*)d_in[2];
    const float* in_b   = (const float*)d_in[3];
    const float* out_w  = (const float*)d_in[4];
    const float* out_b  = (const float*)d_in[5];
    const float* lag    = (const float*)d_in[6];
    const float* cw1    = (const float*)d_in[7];
    const float* cb1    = (const float*)d_in[8];
    const float* cw2    = (const float*)d_in[9];
    const float* cb2    = (const float*)d_in[10];
    const float* gw1    = (const float*)d_in[11];
    const float* gb1    = (const float*)d_in[12];
    const float* gw2    = (const float*)d_in[13];
    const float* gb2    = (const float*)d_in[14];
    const float* lng    = (const float*)d_in[15];
    const float* lnb    = (const float*)d_in[16];
    float* out = (float*)d_out;

    cudaFuncSetAttribute(k_agg, cudaFuncAttributeMaxDynamicSharedMemorySize, AGG_SMEM);
    cudaFuncSetAttribute(k_epi, cudaFuncAttributeMaxDynamicSharedMemorySize, EPI_SMEM);

    k_ctx_partial<<<dim3(32, Bb), 256>>>(x);
    k_small<<<1, 64>>>(lag, cw1, cb1, cw2, cb2, gw1, gb1, gw2, gb2);
    k_normA<<<Kk * Nn, 256>>>(A_list);
    k_convA<<<dim3(512, Bb), 256>>>();
    k_owT<<<256, 256>>>(out_w);
    k_ht<<<dim3(Nn / 32, Tt, Bb), 256>>>(x, in_w, in_b);
    k_agg<<<dim3(4, Tt, Bb), 256, AGG_SMEM>>>();
    k_epi<<<dim3(Nn / 64, Tt, Bb), 256, EPI_SMEM>>>(out_b, lng, lnb, out);
}